// round 1
// baseline (speedup 1.0000x reference)
#include <cuda_runtime.h>
#include <cuda_bf16.h>

#define S_   4096
#define D_   1024
#define B_   8
#define L_   16
#define NC_  19                 // s-chunks per batch  -> 8*19 = 152 CTAs = #SMs
#define TS_  216                // ceil(4096/19); last chunk = 208
#define NCTA_ (B_*NC_)

// Scratch (allocation-free rule: __device__ globals)
__device__ float g_e[B_*L_*S_];      // exp(scores)  (2 MB)
__device__ float g_c[B_*L_];         // w[l] / Z[b,l]
__device__ float g_part[NCTA_*D_];   // per-chunk partial outputs (622 KB)

__device__ __forceinline__ unsigned long long ffma2(unsigned long long a,
                                                    unsigned long long b,
                                                    unsigned long long c) {
    unsigned long long d;
    asm("fma.rn.f32x2 %0, %1, %2, %3;" : "=l"(d) : "l"(a), "l"(b), "l"(c));
    return d;
}

// ---------------------------------------------------------------------------
// Kernel A: e[b,l,s] = exp( (summ[l,:] . mem[b,s,:]) / 32 )
// One thread per s-row; summarizer staged in smem (2 phases of 32KB);
// K-dim packed into f32x2 FMAs (2 MACs per FFMA2 instruction).
// ---------------------------------------------------------------------------
__global__ void __launch_bounds__(256, 1)
kScores(const float* __restrict__ mem, const float* __restrict__ summ) {
    __shared__ __align__(16) float ssum[L_ * 512];

    const int bx  = blockIdx.x;
    const int b   = bx / NC_;
    const int ch  = bx % NC_;
    const int s0  = ch * TS_;
    const int cnt = min(TS_, S_ - s0);
    const int tid = threadIdx.x;
    const bool active = (tid < cnt);
    const int s = s0 + tid;

    unsigned long long acc[L_];
#pragma unroll
    for (int l = 0; l < L_; ++l) acc[l] = 0ULL;

    const ulonglong2* mrow = (const ulonglong2*)(mem + ((size_t)b * S_ + (active ? s : s0)) * D_);

    for (int ph = 0; ph < 2; ++ph) {
        // stage summ[l][ph*512 .. ph*512+511] into smem (coalesced)
        for (int i = tid; i < L_ * 512; i += 256) {
            int l = i >> 9, j = i & 511;
            ssum[i] = summ[l * D_ + ph * 512 + j];
        }
        __syncthreads();
        if (active) {
            const ulonglong2* mp = mrow + ph * 128;   // 128 x 16B = 512 floats
#pragma unroll 4
            for (int i = 0; i < 128; ++i) {
                ulonglong2 m = mp[i];                 // 4 consecutive d values
#pragma unroll
                for (int l = 0; l < L_; ++l) {
                    // broadcast LDS.128: summ[l][4i..4i+3]
                    ulonglong2 sv = *(const ulonglong2*)&ssum[l * 512 + 4 * i];
                    acc[l] = ffma2(sv.x, m.x, acc[l]);
                    acc[l] = ffma2(sv.y, m.y, acc[l]);
                }
            }
        }
        __syncthreads();
    }

    if (active) {
#pragma unroll
        for (int l = 0; l < L_; ++l) {
            union { unsigned long long u; float2 f; } cv; cv.u = acc[l];
            float sc = (cv.f.x + cv.f.y) * 0.03125f;   // / sqrt(1024)
            g_e[((b * L_ + l) * S_) + s] = __expf(sc); // scores are O(0.05): no max needed
        }
    }
}

// ---------------------------------------------------------------------------
// Kernel B: Z[b,l] = sum_s e ;  c[b,l] = w[l] / Z[b,l].  One block per (b,l).
// ---------------------------------------------------------------------------
__global__ void kNorm(const float* __restrict__ wproj) {
    const int row = blockIdx.x;             // b*16 + l
    const int tid = threadIdx.x;
    const float* e = g_e + (size_t)row * S_;
    float v = 0.f;
    for (int i = tid; i < S_; i += 256) v += e[i];
#pragma unroll
    for (int o = 16; o > 0; o >>= 1) v += __shfl_xor_sync(0xFFFFFFFFu, v, o);
    __shared__ float red[8];
    if ((tid & 31) == 0) red[tid >> 5] = v;
    __syncthreads();
    if (tid == 0) {
        float Z = 0.f;
#pragma unroll
        for (int w = 0; w < 8; ++w) Z += red[w];
        g_c[row] = wproj[row & (L_ - 1)] / Z;
    }
}

// ---------------------------------------------------------------------------
// Kernel C: q[s] = sum_l c[b,l]*e[b,l,s]  (in smem), then
//           part[cta, d] = sum_{s in chunk} q[s] * mem[b,s,d]
// Thread t owns d = 4t..4t+3 -> coalesced float4 stream of memory.
// ---------------------------------------------------------------------------
__global__ void __launch_bounds__(256, 1)
kCtx(const float* __restrict__ mem) {
    const int bx  = blockIdx.x;
    const int b   = bx / NC_;
    const int ch  = bx % NC_;
    const int s0  = ch * TS_;
    const int cnt = min(TS_, S_ - s0);
    const int tid = threadIdx.x;

    __shared__ float qs[TS_];
    __shared__ float cs[L_];
    if (tid < L_) cs[tid] = g_c[b * L_ + tid];
    __syncthreads();
    if (tid < cnt) {
        const int s = s0 + tid;
        float q = 0.f;
#pragma unroll
        for (int l = 0; l < L_; ++l) q += cs[l] * g_e[(b * L_ + l) * S_ + s];
        qs[tid] = q;
    }
    __syncthreads();

    const float4* mb = (const float4*)(mem + ((size_t)b * S_ + s0) * D_);
    float4 a = make_float4(0.f, 0.f, 0.f, 0.f);
#pragma unroll 4
    for (int i = 0; i < cnt; ++i) {
        float4 m = mb[(size_t)i * 256 + tid];
        float q = qs[i];                      // broadcast LDS
        a.x += q * m.x; a.y += q * m.y; a.z += q * m.z; a.w += q * m.w;
    }
    ((float4*)(g_part + (size_t)bx * D_))[tid] = a;
}

// ---------------------------------------------------------------------------
// Kernel D: out[b,d] = sum over the 19 chunk partials (deterministic reduce).
// ---------------------------------------------------------------------------
__global__ void kOut(float* __restrict__ out) {
    const int idx = blockIdx.x * 256 + threadIdx.x;    // 0..8191
    const int b = idx >> 10, d = idx & (D_ - 1);
    float acc = 0.f;
#pragma unroll
    for (int c = 0; c < NC_; ++c) acc += g_part[(size_t)(b * NC_ + c) * D_ + d];
    out[idx] = acc;
}

// ---------------------------------------------------------------------------
extern "C" void kernel_launch(void* const* d_in, const int* in_sizes, int n_in,
                              void* d_out, int out_size) {
    const float* mem = nullptr;
    const float* summ = nullptr;
    const float* w = nullptr;
    for (int i = 0; i < n_in; ++i) {               // map by element count (robust)
        if      (in_sizes[i] == B_ * S_ * D_) mem  = (const float*)d_in[i];
        else if (in_sizes[i] == L_ * D_)      summ = (const float*)d_in[i];
        else if (in_sizes[i] == L_)           w    = (const float*)d_in[i];
    }
    kScores<<<NCTA_, 256>>>(mem, summ);
    kNorm  <<<B_ * L_, 256>>>(w);
    kCtx   <<<NCTA_, 256>>>(mem);
    kOut   <<<32, 256>>>((float*)d_out);
}

// round 2
// speedup vs baseline: 1.0701x; 1.0701x over previous
#include <cuda_runtime.h>
#include <cstdint>

#define B_    8
#define S_    4096
#define D_    1024
#define L_    16

// ---- kernel A geometry ----
#define ABLK  128          // blocks: 32768 rows / 256
#define AROWS 256          // s-rows per block (rows t and t+128 per thread)
#define ATHR  128
#define DC    64           // d-chunk width
#define NCH   (D_/DC)      // 16 chunks
#define PITCH 68           // padded floats per tile row (16B aligned, 4-phase LDS)
#define TILEF (AROWS*PITCH)         // 17408 floats per buffer
#define SUMMF (L_*D_)               // 16384 floats
#define OFF_T0 0
#define OFF_T1 TILEF
#define OFF_SU (2*TILEF)            // 34816
#define OFF_WR (OFF_SU + SUMMF)     // 51200  (4 warps x 16 l)
#define SMEMA_BYTES ((OFF_WR + 4*L_) * 4)   // 205,312 B

// ---- kernel C geometry ----
#define CBLK  128
#define CROWS 256

// device scratch (allocation-free rule)
__device__ float g_e[B_*L_*S_];        // exp(scores)   2 MB
__device__ float g_zpart[ABLK*L_];     // per-A-block partial Z
__device__ float g_part[CBLK*D_];      // per-C-block partial ctx
__device__ int   g_cnt[B_];            // arrival counters (reset by kernel A)

__device__ __forceinline__ unsigned long long ffma2(unsigned long long a,
                                                    unsigned long long b,
                                                    unsigned long long c) {
    unsigned long long d;
    asm("fma.rn.f32x2 %0, %1, %2, %3;" : "=l"(d) : "l"(a), "l"(b), "l"(c));
    return d;
}

__device__ __forceinline__ void cpa16(uint32_t saddr, const void* gaddr) {
    asm volatile("cp.async.ca.shared.global [%0], [%1], 16;\n" :: "r"(saddr), "l"(gaddr));
}

// ---------------------------------------------------------------------------
// Kernel A: e[b,l,s] = exp( dot(summ[l], mem[b,s]) / 32 )  + per-block Z partials
// ---------------------------------------------------------------------------
__global__ void __launch_bounds__(ATHR, 1)
kA(const float* __restrict__ mem, const float* __restrict__ summ) {
    extern __shared__ float sA[];
    const int t   = threadIdx.x;
    const int bx  = blockIdx.x;
    const uint32_t sbase = (uint32_t)__cvta_generic_to_shared(sA);

    if (bx < B_ && t == 0) g_cnt[bx] = 0;     // reset kernel-C counters each launch

    // full summarizer -> smem (coalesced, overlapped with first cp.async stage)
    {
        const float4* sg = (const float4*)summ;
        float4* ss = (float4*)&sA[OFF_SU];
#pragma unroll
        for (int k = 0; k < SUMMF/4/ATHR; ++k)       // 32 float4 per thread
            ss[k*ATHR + t] = sg[k*ATHR + t];
    }

    // cp.async staging: tile chunk c into buffer buf. 256 rows x 64 floats.
    const int r0  = t >> 4;                   // 0..7
    const int col = (t & 15) * 4;             // 0..60
    const float* gbase = mem + (size_t)bx * AROWS * D_;

#define STAGE(c, buf)  do {                                                        \
        const float* gp = gbase + (size_t)(c)*DC + r0*D_ + col;                    \
        uint32_t sp = sbase + 4u*((buf)*TILEF + r0*PITCH + col);                   \
        _Pragma("unroll")                                                          \
        for (int k = 0; k < 32; ++k)                                               \
            cpa16(sp + 4u*(8*k*PITCH), gp + (size_t)(8*k)*D_);                     \
        asm volatile("cp.async.commit_group;\n" ::: "memory");                     \
    } while (0)

    unsigned long long acc0[L_], acc1[L_];
#pragma unroll
    for (int l = 0; l < L_; ++l) { acc0[l] = 0ULL; acc1[l] = 0ULL; }

    STAGE(0, 0);

    for (int c = 0; c < NCH; ++c) {
        if (c + 1 < NCH) {
            STAGE(c + 1, (c + 1) & 1);
            asm volatile("cp.async.wait_group 1;\n" ::: "memory");
        } else {
            asm volatile("cp.async.wait_group 0;\n" ::: "memory");
        }
        __syncthreads();

        const int buf = c & 1;
        const ulonglong2* r0p = (const ulonglong2*)&sA[buf*TILEF + t*PITCH];
        const ulonglong2* r1p = (const ulonglong2*)&sA[buf*TILEF + (t+128)*PITCH];
        const ulonglong2* sp  = (const ulonglong2*)&sA[OFF_SU + c*DC];

#pragma unroll 4
        for (int j = 0; j < DC/4; ++j) {          // 16 d-groups of 4
            const ulonglong2 m0 = r0p[j];
            const ulonglong2 m1 = r1p[j];
#pragma unroll
            for (int l = 0; l < L_; ++l) {
                const ulonglong2 sv = sp[l*(D_/4) + j];   // broadcast LDS.128
                acc0[l] = ffma2(sv.x, m0.x, acc0[l]);
                acc0[l] = ffma2(sv.y, m0.y, acc0[l]);
                acc1[l] = ffma2(sv.x, m1.x, acc1[l]);
                acc1[l] = ffma2(sv.y, m1.y, acc1[l]);
            }
        }
        __syncthreads();
    }

    // epilogue: exp, store e, per-block partial Z
    const int b   = bx >> 4;
    const int sch = (bx & 15) << 8;
    const int wid = t >> 5, lid = t & 31;
    float* wred = &sA[OFF_WR];

#pragma unroll
    for (int l = 0; l < L_; ++l) {
        union { unsigned long long u; float2 f; } c0, c1;
        c0.u = acc0[l]; c1.u = acc1[l];
        float e0 = __expf((c0.f.x + c0.f.y) * 0.03125f);   // scores ~O(0.05): no max sub
        float e1 = __expf((c1.f.x + c1.f.y) * 0.03125f);
        float* ep = g_e + ((size_t)(b*L_ + l) << 12) + sch + t;
        ep[0]   = e0;
        ep[128] = e1;
        float v = e0 + e1;
#pragma unroll
        for (int o = 16; o > 0; o >>= 1) v += __shfl_xor_sync(0xFFFFFFFFu, v, o);
        if (lid == 0) wred[wid*L_ + l] = v;
    }
    __syncthreads();
    if (t < L_) {
        float zp = wred[t] + wred[L_ + t] + wred[2*L_ + t] + wred[3*L_ + t];
        g_zpart[bx*L_ + t] = zp;
    }
#undef STAGE
}

// ---------------------------------------------------------------------------
// Kernel C: c=w/Z, q[s]=sum_l c_l*e_ls, partial out = sum_s q*mem,
//           last block per batch reduces the 16 partials (fixed order).
// ---------------------------------------------------------------------------
__global__ void __launch_bounds__(256, 1)
kC(const float* __restrict__ mem, const float* __restrict__ wproj,
   float* __restrict__ out) {
    const int t  = threadIdx.x;
    const int bx = blockIdx.x;
    const int b  = bx >> 4;
    const int s0 = (bx & 15) << 8;

    __shared__ float zs[256];
    __shared__ float cs[L_];
    __shared__ float qs[CROWS];
    __shared__ int lastFlag;

    zs[t] = g_zpart[b*256 + t];               // [j=0..15][l=0..15] of this batch
    __syncthreads();
    if (t < L_) {
        float Z = 0.f;
#pragma unroll
        for (int j = 0; j < 16; ++j) Z += zs[j*L_ + t];
        cs[t] = wproj[t] / Z;
    }
    __syncthreads();

    {   // q for this block's 256 s-rows
        const float* ep = g_e + ((size_t)b*L_ << 12) + s0 + t;
        float q = 0.f;
#pragma unroll
        for (int l = 0; l < L_; ++l) q += cs[l] * ep[(size_t)l << 12];
        qs[t] = q;
    }
    __syncthreads();

    // HBM-bound pass: thread owns float4 column t
    const float4* mp = (const float4*)mem + ((size_t)(b*S_ + s0)) * (D_/4) + t;
    float4 a = make_float4(0.f, 0.f, 0.f, 0.f);
#pragma unroll 8
    for (int i = 0; i < CROWS; ++i) {
        float4 m = mp[(size_t)i * (D_/4)];
        float q = qs[i];
        a.x += q*m.x; a.y += q*m.y; a.z += q*m.z; a.w += q*m.w;
    }
    ((float4*)g_part)[bx*(D_/4) + t] = a;

    __threadfence();
    __syncthreads();
    if (t == 0) lastFlag = (atomicAdd(&g_cnt[b], 1) == 15);
    __syncthreads();

    if (lastFlag) {
        __threadfence();
        float4 r = make_float4(0.f, 0.f, 0.f, 0.f);
#pragma unroll
        for (int j = 0; j < 16; ++j) {
            float4 p = ((const float4*)g_part)[(b*16 + j)*(D_/4) + t];
            r.x += p.x; r.y += p.y; r.z += p.z; r.w += p.w;
        }
        ((float4*)out)[b*(D_/4) + t] = r;
    }
}

// ---------------------------------------------------------------------------
extern "C" void kernel_launch(void* const* d_in, const int* in_sizes, int n_in,
                              void* d_out, int out_size) {
    const float* mem = nullptr;
    const float* summ = nullptr;
    const float* w = nullptr;
    for (int i = 0; i < n_in; ++i) {
        if      (in_sizes[i] == B_*S_*D_) mem  = (const float*)d_in[i];
        else if (in_sizes[i] == L_*D_)    summ = (const float*)d_in[i];
        else if (in_sizes[i] == L_)       w    = (const float*)d_in[i];
    }
    static bool attrDone = false;
    if (!attrDone) {
        cudaFuncSetAttribute(kA, cudaFuncAttributeMaxDynamicSharedMemorySize, SMEMA_BYTES);
        attrDone = true;
    }
    kA<<<ABLK, ATHR, SMEMA_BYTES>>>(mem, summ);
    kC<<<CBLK, 256>>>(mem, w, (float*)d_out);
}